// round 1
// baseline (speedup 1.0000x reference)
#include <cuda_runtime.h>

// Problem constants
#define NROW 4096      // rows per set
#define NS   8192      // total rows (source + target)
#define DD   128       // feature dim
#define NT   128       // 64-row tiles per dimension (8192/64)
#define BM   64        // tile size (M and N)
#define KC   64        // k-chunk (two chunks cover D=128)

// Scratch (no allocations allowed -> __device__ globals)
__device__ float  g_sq[NS];
__device__ double g_sumsq;
__device__ double g_sumvec[DD];
__device__ float  g_coef[5];
__device__ double g_acc;

// ---------------------------------------------------------------------------
// 0) zero accumulators (graph replays re-run this)
__global__ void init_kernel() {
    int t = threadIdx.x;
    if (t == 0) { g_sumsq = 0.0; g_acc = 0.0; }
    if (t < DD) g_sumvec[t] = 0.0;
}

// ---------------------------------------------------------------------------
// 1) per-row squared norms + total sum of squares. One warp per row.
__global__ void rowstats_kernel(const float* __restrict__ src,
                                const float* __restrict__ tgt) {
    int warp = threadIdx.x >> 5, lane = threadIdx.x & 31;
    int r = blockIdx.x * 8 + warp;
    const float* p = (r < NROW) ? (src + (size_t)r * DD)
                                : (tgt + (size_t)(r - NROW) * DD);
    float4 v = ((const float4*)p)[lane];
    float s = v.x * v.x + v.y * v.y + v.z * v.z + v.w * v.w;
    #pragma unroll
    for (int o = 16; o > 0; o >>= 1) s += __shfl_down_sync(0xffffffffu, s, o);
    if (lane == 0) {
        g_sq[r] = s;
        atomicAdd(&g_sumsq, (double)s);
    }
}

// ---------------------------------------------------------------------------
// 2) column sums (for ||sum_vec||^2 in the bandwidth identity)
__global__ void colsum_kernel(const float* __restrict__ src,
                              const float* __restrict__ tgt) {
    int d = threadIdx.x;              // 128 threads
    int r0 = blockIdx.x * 256;        // 32 blocks x 256 rows
    double acc = 0.0;
    for (int i = 0; i < 256; i++) {
        int r = r0 + i;
        const float* p = (r < NROW) ? (src + (size_t)r * DD)
                                    : (tgt + (size_t)(r - NROW) * DD);
        acc += (double)p[d];
    }
    atomicAdd(&g_sumvec[d], acc);
}

// ---------------------------------------------------------------------------
// 3) bandwidth: sum(L2) = 2*ns*sum_sq - 2*||sum_vec||^2, exact in double.
//    bw = sum(L2)/(ns^2 - ns) / KERNEL_MUL^(KERNEL_NUM//2) = .../4
//    coef[i] = -1/(bw * 2^i)
__global__ void bw_kernel() {
    __shared__ double sh[128];
    int d = threadIdx.x;
    double v = g_sumvec[d];
    sh[d] = v * v;
    __syncthreads();
    for (int o = 64; o > 0; o >>= 1) {
        if (d < o) sh[d] += sh[d + o];
        __syncthreads();
    }
    if (d == 0) {
        double sumL2 = 2.0 * (double)NS * g_sumsq - 2.0 * sh[0];
        double bw = sumL2 / ((double)NS * (double)NS - (double)NS) / 4.0;
        #pragma unroll
        for (int i = 0; i < 5; i++)
            g_coef[i] = (float)(-1.0 / (bw * (double)(1 << i)));
    }
}

// ---------------------------------------------------------------------------
// 4) main tile kernel: signed sum of 5-kernel Gaussian values over the
//    upper-triangular tile set (bi <= bj), weight 2 off-diagonal.
__global__ __launch_bounds__(256)
void mmd_kernel(const float* __restrict__ src, const float* __restrict__ tgt) {
    int bj = blockIdx.x, bi = blockIdx.y;
    if (bi > bj) return;  // symmetry: upper triangle only

    __shared__ float As[KC][BM];   // [k][m], transposed for vector compute reads
    __shared__ float Bs[KC][BM];   // [k][n]

    int tid = threadIdx.x;
    int tx = tid & 15, ty = tid >> 4;      // 16x16 threads, 4x4 micro-tile
    int lm  = tid & 63;                    // loader: m index (conflict-free STS)
    int lk4 = tid >> 6;                    // loader: base float4-k group (0..3)

    const float* pa = (bi < NT / 2) ? src + (size_t)bi * BM * DD
                                    : tgt + (size_t)(bi - NT / 2) * BM * DD;
    const float* pb = (bj < NT / 2) ? src + (size_t)bj * BM * DD
                                    : tgt + (size_t)(bj - NT / 2) * BM * DD;

    float acc[4][4] = {};

    #pragma unroll
    for (int kc = 0; kc < 2; kc++) {
        int k0 = kc * KC;
        __syncthreads();
        #pragma unroll
        for (int j = 0; j < 4; j++) {
            int k4 = lk4 + j * 4;  // 0..15 (KC/4 float4 groups)
            float4 va = *(const float4*)(pa + (size_t)lm * DD + k0 + k4 * 4);
            float4 vb = *(const float4*)(pb + (size_t)lm * DD + k0 + k4 * 4);
            As[k4 * 4 + 0][lm] = va.x; As[k4 * 4 + 1][lm] = va.y;
            As[k4 * 4 + 2][lm] = va.z; As[k4 * 4 + 3][lm] = va.w;
            Bs[k4 * 4 + 0][lm] = vb.x; Bs[k4 * 4 + 1][lm] = vb.y;
            Bs[k4 * 4 + 2][lm] = vb.z; Bs[k4 * 4 + 3][lm] = vb.w;
        }
        __syncthreads();
        #pragma unroll
        for (int k = 0; k < KC; k++) {
            float4 a = *(const float4*)&As[k][ty * 4];
            float4 b = *(const float4*)&Bs[k][tx * 4];
            acc[0][0] += a.x * b.x; acc[0][1] += a.x * b.y;
            acc[0][2] += a.x * b.z; acc[0][3] += a.x * b.w;
            acc[1][0] += a.y * b.x; acc[1][1] += a.y * b.y;
            acc[1][2] += a.y * b.z; acc[1][3] += a.y * b.w;
            acc[2][0] += a.z * b.x; acc[2][1] += a.z * b.y;
            acc[2][2] += a.z * b.z; acc[2][3] += a.z * b.w;
            acc[3][0] += a.w * b.x; acc[3][1] += a.w * b.y;
            acc[3][2] += a.w * b.z; acc[3][3] += a.w * b.w;
        }
    }

    // Epilogue: L2 -> 5 Gaussian kernels -> signed local sum
    float c0 = g_coef[0], c1 = g_coef[1], c2 = g_coef[2],
          c3 = g_coef[3], c4 = g_coef[4];
    int i0 = bi * BM + ty * 4;
    int j0 = bj * BM + tx * 4;
    float sqa[4], sqb[4];
    #pragma unroll
    for (int u = 0; u < 4; u++) sqa[u] = g_sq[i0 + u];
    #pragma unroll
    for (int v = 0; v < 4; v++) sqb[v] = g_sq[j0 + v];

    float local = 0.f;
    #pragma unroll
    for (int u = 0; u < 4; u++) {
        #pragma unroll
        for (int v = 0; v < 4; v++) {
            float l2 = sqa[u] + sqb[v] - 2.f * acc[u][v];
            local += __expf(l2 * c0) + __expf(l2 * c1) + __expf(l2 * c2)
                   + __expf(l2 * c3) + __expf(l2 * c4);
        }
    }

    float sign = ((bi < NT / 2) == (bj < NT / 2)) ? 1.f : -1.f;
    float w = sign * ((bi == bj) ? 1.f : 2.f);
    local *= w;

    // Block reduction -> one double atomic per block
    #pragma unroll
    for (int o = 16; o > 0; o >>= 1)
        local += __shfl_down_sync(0xffffffffu, local, o);
    __shared__ float red[8];
    if ((tid & 31) == 0) red[tid >> 5] = local;
    __syncthreads();
    if (tid < 8) {
        float s = red[tid];
        #pragma unroll
        for (int o = 4; o > 0; o >>= 1)
            s += __shfl_down_sync(0x000000ffu, s, o);
        if (tid == 0) atomicAdd(&g_acc, (double)s);
    }
}

// ---------------------------------------------------------------------------
// 5) finalize: mean over n x n
__global__ void fin_kernel(float* out) {
    out[0] = (float)(g_acc / ((double)NROW * (double)NROW));
}

extern "C" void kernel_launch(void* const* d_in, const int* in_sizes, int n_in,
                              void* d_out, int out_size) {
    const float* src = (const float*)d_in[0];
    const float* tgt = (const float*)d_in[1];
    float* out = (float*)d_out;

    init_kernel<<<1, 128>>>();
    rowstats_kernel<<<NS / 8, 256>>>(src, tgt);
    colsum_kernel<<<NS / 256, 128>>>(src, tgt);
    bw_kernel<<<1, 128>>>();
    mmd_kernel<<<dim3(NT, NT), 256>>>(src, tgt);
    fin_kernel<<<1, 1>>>(out);
}

// round 3
// speedup vs baseline: 4.5558x; 4.5558x over previous
#include <cuda_runtime.h>
#include <cstdint>

#define NROW 4096
#define NS   8192
#define DD   128
#define TB   128      // output tile (M=N=128)
#define NTB  64       // NS/TB tiles per dim
#define NTILES 2080   // NTB*(NTB+1)/2 upper-triangular tiles
#define LDS_STRIDE 132  // padded row stride (floats) -> conflict-free

// -------- device globals (no allocations allowed) --------
__device__ float  g_sq[NS];
__device__ double g_sumsq;
__device__ double g_sumvec[DD];
__device__ float  g_c;       // -1/(bw*16)
__device__ double g_acc;

// ---------------------------------------------------------------------------
__global__ void init_kernel() {
    int t = threadIdx.x;
    if (t == 0) { g_sumsq = 0.0; g_acc = 0.0; }
    if (t < DD) g_sumvec[t] = 0.0;
}

// per-row squared norms + block-reduced total
__global__ void rowstats_kernel(const float* __restrict__ src,
                                const float* __restrict__ tgt) {
    __shared__ double sh[8];
    int warp = threadIdx.x >> 5, lane = threadIdx.x & 31;
    int r = blockIdx.x * 8 + warp;
    const float* p = (r < NROW) ? (src + (size_t)r * DD)
                                : (tgt + (size_t)(r - NROW) * DD);
    float4 v = ((const float4*)p)[lane];
    float s = v.x * v.x + v.y * v.y + v.z * v.z + v.w * v.w;
    #pragma unroll
    for (int o = 16; o > 0; o >>= 1) s += __shfl_down_sync(0xffffffffu, s, o);
    if (lane == 0) { g_sq[r] = s; sh[warp] = (double)s; }
    __syncthreads();
    if (threadIdx.x == 0) {
        double a = 0.0;
        #pragma unroll
        for (int i = 0; i < 8; i++) a += sh[i];
        atomicAdd(&g_sumsq, a);
    }
}

__global__ void colsum_kernel(const float* __restrict__ src,
                              const float* __restrict__ tgt) {
    int d = threadIdx.x;
    int r0 = blockIdx.x * 256;
    double acc = 0.0;
    for (int i = 0; i < 256; i++) {
        int r = r0 + i;
        const float* p = (r < NROW) ? (src + (size_t)r * DD)
                                    : (tgt + (size_t)(r - NROW) * DD);
        acc += (double)p[d];
    }
    atomicAdd(&g_sumvec[d], acc);
}

// bw from exact identity: sum(L2) = 2*ns*sum_sq - 2*||sum_vec||^2
__global__ void bw_kernel() {
    __shared__ double sh[128];
    int d = threadIdx.x;
    double v = g_sumvec[d];
    sh[d] = v * v;
    __syncthreads();
    for (int o = 64; o > 0; o >>= 1) {
        if (d < o) sh[d] += sh[d + o];
        __syncthreads();
    }
    if (d == 0) {
        double sumL2 = 2.0 * (double)NS * g_sumsq - 2.0 * sh[0];
        double bw = sumL2 / ((double)NS * (double)NS - (double)NS) / 4.0;
        g_c = (float)(-1.0 / (bw * 16.0));  // t=exp(c*L2); sum=t+t^2+t^4+t^8+t^16
    }
}

// ---------------------------------------------------------------------------
__device__ __forceinline__ uint32_t f2tf32(float f) {
    uint32_t o;
    asm("cvt.rna.tf32.f32 %0, %1;" : "=r"(o) : "f"(f));
    return o;
}

__device__ __forceinline__ void mma_tf32(float* c, const uint32_t* a,
                                         const uint32_t* b) {
    asm volatile(
        "mma.sync.aligned.m16n8k8.row.col.f32.tf32.tf32.f32 "
        "{%0,%1,%2,%3}, {%4,%5,%6,%7}, {%8,%9}, {%0,%1,%2,%3};"
        : "+f"(c[0]), "+f"(c[1]), "+f"(c[2]), "+f"(c[3])
        : "r"(a[0]), "r"(a[1]), "r"(a[2]), "r"(a[3]), "r"(b[0]), "r"(b[1]));
}

#define SM_X 0
#define SM_Y (TB * LDS_STRIDE)                 // floats
#define SM_TOT_FLOATS (2 * TB * LDS_STRIDE)    // 33792 floats = 135168 B

__global__ __launch_bounds__(256)
void mmd_mma_kernel(const float* __restrict__ src,
                    const float* __restrict__ tgt) {
    extern __shared__ float smem[];
    float* Xs = smem + SM_X;
    float* Ys = smem + SM_Y;

    // triangular decode: linear tile -> (bi, bj), bi <= bj
    int t = blockIdx.x;
    int bi = (int)((129.0f - sqrtf(16641.0f - 8.0f * (float)t)) * 0.5f);
    if (bi > NTB - 1) bi = NTB - 1;
    if (bi < 0) bi = 0;
    while (bi * NTB - bi * (bi - 1) / 2 > t) bi--;
    while ((bi + 1) * NTB - (bi + 1) * bi / 2 <= t) bi++;
    int bj = bi + (t - (bi * NTB - bi * (bi - 1) / 2));

    int tid = threadIdx.x, wid = tid >> 5, lane = tid & 31;
    int wr = wid >> 2, wc = wid & 3;       // warp grid 2x4 (64-row x 32-col)
    int lr = lane >> 2, lc = lane & 3;

    const float* gA = (bi < NTB / 2) ? src + (size_t)bi * TB * DD
                                     : tgt + (size_t)(bi - NTB / 2) * TB * DD;
    const float* gB = (bj < NTB / 2) ? src + (size_t)bj * TB * DD
                                     : tgt + (size_t)(bj - NTB / 2) * TB * DD;

    // fill smem with tf32-rounded values (coalesced LDG, conflict-free STS)
    #pragma unroll
    for (int i = 0; i < 16; i++) {
        int idx = tid + i * 256;             // 4096 float4 per image
        int r = idx >> 5, c4 = (idx & 31) << 2;
        float4 va = *(const float4*)(gA + (size_t)r * DD + c4);
        float4 vb = *(const float4*)(gB + (size_t)r * DD + c4);
        uint4 ta = make_uint4(f2tf32(va.x), f2tf32(va.y), f2tf32(va.z), f2tf32(va.w));
        uint4 tb = make_uint4(f2tf32(vb.x), f2tf32(vb.y), f2tf32(vb.z), f2tf32(vb.w));
        *(uint4*)(Xs + r * LDS_STRIDE + c4) = ta;
        *(uint4*)(Ys + r * LDS_STRIDE + c4) = tb;
    }
    __syncthreads();

    // mainloop: warp computes 64x32 via 4x4 m16n8k8 tiles over 16 k-steps
    float acc[4][4][4];
    #pragma unroll
    for (int mi = 0; mi < 4; mi++)
        #pragma unroll
        for (int ni = 0; ni < 4; ni++)
            #pragma unroll
            for (int q = 0; q < 4; q++) acc[mi][ni][q] = 0.f;

    const float* Xw = Xs + (wr * 64 + lr) * LDS_STRIDE + lc;
    const float* Yw = Ys + (wc * 32 + lr) * LDS_STRIDE + lc;

    for (int k0 = 0; k0 < DD; k0 += 8) {
        uint32_t a[4][4], b[4][2];
        #pragma unroll
        for (int mi = 0; mi < 4; mi++) {
            const float* p = Xw + mi * 16 * LDS_STRIDE + k0;
            a[mi][0] = __float_as_uint(p[0]);
            a[mi][1] = __float_as_uint(p[8 * LDS_STRIDE]);
            a[mi][2] = __float_as_uint(p[4]);
            a[mi][3] = __float_as_uint(p[8 * LDS_STRIDE + 4]);
        }
        #pragma unroll
        for (int ni = 0; ni < 4; ni++) {
            const float* p = Yw + ni * 8 * LDS_STRIDE + k0;
            b[ni][0] = __float_as_uint(p[0]);
            b[ni][1] = __float_as_uint(p[4]);
        }
        #pragma unroll
        for (int mi = 0; mi < 4; mi++)
            #pragma unroll
            for (int ni = 0; ni < 4; ni++)
                mma_tf32(acc[mi][ni], a[mi], b[ni]);
    }

    // epilogue: L2 -> fused 5-kernel Gaussian via t-powers
    float c = g_c;
    float sqa[4][2], sqb[4][2];
    #pragma unroll
    for (int mi = 0; mi < 4; mi++) {
        int r0 = bi * TB + wr * 64 + mi * 16 + lr;
        sqa[mi][0] = g_sq[r0];
        sqa[mi][1] = g_sq[r0 + 8];
    }
    #pragma unroll
    for (int ni = 0; ni < 4; ni++) {
        int c0 = bj * TB + wc * 32 + ni * 8 + lc * 2;
        sqb[ni][0] = g_sq[c0];
        sqb[ni][1] = g_sq[c0 + 1];
    }

    float local = 0.f;
    #pragma unroll
    for (int mi = 0; mi < 4; mi++) {
        #pragma unroll
        for (int ni = 0; ni < 4; ni++) {
            #pragma unroll
            for (int q = 0; q < 4; q++) {
                float sa = sqa[mi][q >> 1];
                float sb = sqb[ni][q & 1];
                float l2 = fmaf(-2.f, acc[mi][ni][q], sa + sb);
                float tv = __expf(l2 * c);
                float t2 = tv * tv, t4 = t2 * t2, t8 = t4 * t4;
                local += (tv + t2) + (t4 + (t8 + t8 * t8));
            }
        }
    }
    float wgt = (((bi < NTB / 2) == (bj < NTB / 2)) ? 1.f : -1.f)
              * ((bi == bj) ? 1.f : 2.f);
    local *= wgt;

    #pragma unroll
    for (int o = 16; o > 0; o >>= 1)
        local += __shfl_down_sync(0xffffffffu, local, o);
    __shared__ float red[8];
    if (lane == 0) red[wid] = local;
    __syncthreads();
    if (tid == 0) {
        float s = 0.f;
        #pragma unroll
        for (int i = 0; i < 8; i++) s += red[i];
        atomicAdd(&g_acc, (double)s);
    }
}

__global__ void fin_kernel(float* out) {
    out[0] = (float)(g_acc / ((double)NROW * (double)NROW));
}

// ---------------------------------------------------------------------------
extern "C" void kernel_launch(void* const* d_in, const int* in_sizes, int n_in,
                              void* d_out, int out_size) {
    const float* src = (const float*)d_in[0];
    const float* tgt = (const float*)d_in[1];
    float* out = (float*)d_out;

    cudaFuncSetAttribute(mmd_mma_kernel,
                         cudaFuncAttributeMaxDynamicSharedMemorySize,
                         SM_TOT_FLOATS * 4);

    init_kernel<<<1, 128>>>();
    rowstats_kernel<<<NS / 8, 256>>>(src, tgt);
    colsum_kernel<<<NS / 256, 128>>>(src, tgt);
    bw_kernel<<<1, 128>>>();
    mmd_mma_kernel<<<NTILES, 256, SM_TOT_FLOATS * 4>>>(src, tgt);
    fin_kernel<<<1, 1>>>(out);
}

// round 5
// speedup vs baseline: 7.2730x; 1.5964x over previous
#include <cuda_runtime.h>
#include <cstdint>

#define NROW 4096
#define NS   8192
#define DD   128
#define TB   128        // output tile (M=N=128)
#define NTB  64         // NS/TB blocks per dim
#define NTILES 2080     // NTB*(NTB+1)/2
#define IMGB 65536      // bytes per permuted tf32 image (128x128 floats)
#define CHB  16384      // bytes per K=32 chunk of one image

// -------- device globals (no allocations allowed) --------
__device__ float  g_sq[NS];
__device__ double g_sumsq;
__device__ double g_sumvec[DD];
__device__ float  g_c;       // -1/(bw*16)
__device__ double g_acc;
__device__ __align__(16) unsigned char g_pa[NTB * IMGB];  // A-fragment layout
__device__ __align__(16) unsigned char g_pb[NTB * IMGB];  // B-fragment layout

// ---------------------------------------------------------------------------
__global__ void init_kernel() {
    int t = threadIdx.x;
    if (t == 0) { g_sumsq = 0.0; g_acc = 0.0; }
    if (t < DD) g_sumvec[t] = 0.0;
}

__device__ __forceinline__ uint32_t f2tf32(float f) {
    uint32_t o;
    asm("cvt.rna.tf32.f32 %0, %1;" : "=r"(o) : "f"(f));
    return o;
}

// ---------------------------------------------------------------------------
// stats + permuted-image prep. One CTA per 128-row block image.
// A-layout: float offset ((ks*8+rb)*32 + (rr&7)*4+lc)*4 + slot,
//   slots = {X[r][kc], X[r+8][kc], X[r][kc+4], X[r+8][kc+4]}, kc=ks*8+lc
// B-layout: float offset ((ks*16+nb)*32 + (n&7)*4+lc)*2 + slot,
//   slots = {X[n][kc], X[n][kc+4]}
__global__ __launch_bounds__(256)
void stats_perm_kernel(const float* __restrict__ src,
                       const float* __restrict__ tgt) {
    __shared__ float rownorm[TB];
    int blk = blockIdx.x, t = threadIdx.x;
    if (t < TB) rownorm[t] = 0.f;
    __syncthreads();

    const float* gX = (blk < NTB / 2) ? src + (size_t)blk * TB * DD
                                      : tgt + (size_t)(blk - NTB / 2) * TB * DD;
    float* pa = (float*)(g_pa + (size_t)blk * IMGB);
    float* pb = (float*)(g_pb + (size_t)blk * IMGB);

    int rr = t & 7, rb = (t >> 3) & 7, q = t >> 6;   // q in 0..3
    int R0 = rb * 16 + rr, R1 = R0 + 8;
    float pn0 = 0.f, pn1 = 0.f;

    #pragma unroll
    for (int u = 0; u < 4; u++) {
        int ks = q * 4 + u;
        float4 f0 = ((const float4*)(gX + (size_t)R0 * DD))[ks * 2];
        float4 f1 = ((const float4*)(gX + (size_t)R0 * DD))[ks * 2 + 1];
        float4 f2 = ((const float4*)(gX + (size_t)R1 * DD))[ks * 2];
        float4 f3 = ((const float4*)(gX + (size_t)R1 * DD))[ks * 2 + 1];
        pn0 += f0.x*f0.x + f0.y*f0.y + f0.z*f0.z + f0.w*f0.w
             + f1.x*f1.x + f1.y*f1.y + f1.z*f1.z + f1.w*f1.w;
        pn1 += f2.x*f2.x + f2.y*f2.y + f2.z*f2.z + f2.w*f2.w
             + f3.x*f3.x + f3.y*f3.y + f3.z*f3.z + f3.w*f3.w;

        uint32_t t0[4] = {f2tf32(f0.x), f2tf32(f0.y), f2tf32(f0.z), f2tf32(f0.w)};
        uint32_t t1[4] = {f2tf32(f1.x), f2tf32(f1.y), f2tf32(f1.z), f2tf32(f1.w)};
        uint32_t t2[4] = {f2tf32(f2.x), f2tf32(f2.y), f2tf32(f2.z), f2tf32(f2.w)};
        uint32_t t3[4] = {f2tf32(f3.x), f2tf32(f3.y), f2tf32(f3.z), f2tf32(f3.w)};

        // A-layout stores: 4 x STG.128
        #pragma unroll
        for (int lc = 0; lc < 4; lc++) {
            uint4 v = make_uint4(t0[lc], t2[lc], t1[lc], t3[lc]);
            *(uint4*)(pa + ((size_t)((ks * 8 + rb) * 32 + rr * 4 + lc) * 4)) = v;
        }
        // B-layout stores: 8 x STG.64 (rows R0 and R1)
        int nb0 = R0 >> 3, nr0 = R0 & 7;
        int nb1 = R1 >> 3, nr1 = R1 & 7;
        #pragma unroll
        for (int lc = 0; lc < 4; lc++) {
            uint2 v0 = make_uint2(t0[lc], t1[lc]);
            uint2 v1 = make_uint2(t2[lc], t3[lc]);
            *(uint2*)(pb + ((size_t)((ks * 16 + nb0) * 32 + nr0 * 4 + lc) * 2)) = v0;
            *(uint2*)(pb + ((size_t)((ks * 16 + nb1) * 32 + nr1 * 4 + lc) * 2)) = v1;
        }
    }
    atomicAdd(&rownorm[R0], pn0);
    atomicAdd(&rownorm[R1], pn1);
    __syncthreads();

    if (t < TB) {
        float v = rownorm[t];
        g_sq[blk * TB + t] = v;
        // warp-reduce then one atomic per warp
        float s = v;
        #pragma unroll
        for (int o = 16; o > 0; o >>= 1) s += __shfl_down_sync(0xffffffffu, s, o);
        if ((t & 31) == 0) atomicAdd(&g_sumsq, (double)s);
    }

    // column partial sums
    {
        int d = t & 127, h = t >> 7;
        const float* p = gX + (size_t)h * 64 * DD + d;
        double a = 0.0;
        #pragma unroll 8
        for (int i = 0; i < 64; i++) a += (double)p[(size_t)i * DD];
        atomicAdd(&g_sumvec[d], a);
    }
}

// bw from exact identity: sum(L2) = 2*ns*sum_sq - 2*||sum_vec||^2
__global__ void bw_kernel() {
    __shared__ double sh[128];
    int d = threadIdx.x;
    double v = g_sumvec[d];
    sh[d] = v * v;
    __syncthreads();
    for (int o = 64; o > 0; o >>= 1) {
        if (d < o) sh[d] += sh[d + o];
        __syncthreads();
    }
    if (d == 0) {
        double sumL2 = 2.0 * (double)NS * g_sumsq - 2.0 * sh[0];
        double bw = sumL2 / ((double)NS * (double)NS - (double)NS) / 4.0;
        g_c = (float)(-1.0 / (bw * 16.0));  // t=exp(c*L2); sum=t+t^2+t^4+t^8+t^16
    }
}

// ---------------------------------------------------------------------------
__device__ __forceinline__ void mma_tf32(float* c, const uint32_t* a,
                                         const uint32_t* b) {
    asm volatile(
        "mma.sync.aligned.m16n8k8.row.col.f32.tf32.tf32.f32 "
        "{%0,%1,%2,%3}, {%4,%5,%6,%7}, {%8,%9}, {%0,%1,%2,%3};"
        : "+f"(c[0]), "+f"(c[1]), "+f"(c[2]), "+f"(c[3])
        : "r"(a[0]), "r"(a[1]), "r"(a[2]), "r"(a[3]), "r"(b[0]), "r"(b[1]));
}

__device__ __forceinline__ uint32_t smem_u32(const void* p) {
    uint32_t a;
    asm("{ .reg .u64 t; cvta.to.shared.u64 t, %1; cvt.u32.u64 %0, t; }"
        : "=r"(a) : "l"(p));
    return a;
}

#define CP16(dst, src) \
    asm volatile("cp.async.cg.shared.global [%0], [%1], 16;" \
                 :: "r"(dst), "l"(src) : "memory")
#define CP_COMMIT() asm volatile("cp.async.commit_group;" ::: "memory")
#define CP_WAIT(n)  asm volatile("cp.async.wait_group %0;" :: "n"(n) : "memory")

// main tensor-core tile kernel: 128x128 tile per CTA, K=32 chunks, dbl-buffered
__global__ __launch_bounds__(256, 2)
void mmd_mma_kernel() {
    extern __shared__ float smem[];   // 2 bufs x (A 16KB + B 16KB) = 64KB
    __shared__ float red[8];

    // triangular decode: linear tile -> (bi, bj), bi <= bj
    int t = blockIdx.x;
    int bi = (int)((129.0f - sqrtf(16641.0f - 8.0f * (float)t)) * 0.5f);
    if (bi > NTB - 1) bi = NTB - 1;
    if (bi < 0) bi = 0;
    while (bi * NTB - bi * (bi - 1) / 2 > t) bi--;
    while ((bi + 1) * NTB - (bi + 1) * bi / 2 <= t) bi++;
    int bj = bi + (t - (bi * NTB - bi * (bi - 1) / 2));

    int tid = threadIdx.x, wid = tid >> 5, lane = tid & 31;
    int wr = wid >> 2, wc = wid & 3;         // warp grid 2x4

    const unsigned char* gA = g_pa + (size_t)bi * IMGB;
    const unsigned char* gB = g_pb + (size_t)bj * IMGB;
    uint32_t sb = smem_u32(smem);

    float acc[4][4][4];
    #pragma unroll
    for (int mi = 0; mi < 4; mi++)
        #pragma unroll
        for (int ni = 0; ni < 4; ni++)
            #pragma unroll
            for (int q = 0; q < 4; q++) acc[mi][ni][q] = 0.f;

    // issue chunk c into buffer c&1
    auto issue = [&](int c) {
        uint32_t base = sb + (uint32_t)(c & 1) * 32768;
        const unsigned char* sA = gA + c * CHB + tid * 16;
        const unsigned char* sB = gB + c * CHB + tid * 16;
        #pragma unroll
        for (int i = 0; i < 4; i++) {
            CP16(base + tid * 16 + i * 4096, sA + i * 4096);
            CP16(base + 16384 + tid * 16 + i * 4096, sB + i * 4096);
        }
        CP_COMMIT();
    };

    issue(0);
    #pragma unroll
    for (int c = 0; c < 4; c++) {
        if (c < 3) { issue(c + 1); CP_WAIT(1); }
        else       { CP_WAIT(0); }
        __syncthreads();
        const float* Ab = smem + (c & 1) * 8192;
        const float* Bb = Ab + 4096;
        #pragma unroll
        for (int ks = 0; ks < 4; ks++) {
            uint32_t a[4][4], b[4][2];
            #pragma unroll
            for (int mi = 0; mi < 4; mi++) {
                uint4 v = *(const uint4*)(Ab + ((ks * 8 + wr * 4 + mi) * 32 + lane) * 4);
                a[mi][0] = v.x; a[mi][1] = v.y; a[mi][2] = v.z; a[mi][3] = v.w;
            }
            #pragma unroll
            for (int ni = 0; ni < 4; ni++) {
                uint2 v = *(const uint2*)(Bb + ((ks * 16 + wc * 4 + ni) * 32 + lane) * 2);
                b[ni][0] = v.x; b[ni][1] = v.y;
            }
            #pragma unroll
            for (int mi = 0; mi < 4; mi++)
                #pragma unroll
                for (int ni = 0; ni < 4; ni++)
                    mma_tf32(acc[mi][ni], a[mi], b[ni]);
        }
        __syncthreads();
    }

    // epilogue: L2 -> fused 5-kernel Gaussian via t-powers
    int lr = lane >> 2, lc = lane & 3;
    float c2 = g_c * 1.4426950408889634f;   // for exp2f
    float sqa[4][2], sqb[4][2];
    #pragma unroll
    for (int mi = 0; mi < 4; mi++) {
        int r0 = bi * TB + wr * 64 + mi * 16 + lr;
        sqa[mi][0] = g_sq[r0];
        sqa[mi][1] = g_sq[r0 + 8];
    }
    #pragma unroll
    for (int ni = 0; ni < 4; ni++) {
        int c0 = bj * TB + wc * 32 + ni * 8 + lc * 2;
        sqb[ni][0] = g_sq[c0];
        sqb[ni][1] = g_sq[c0 + 1];
    }

    float local = 0.f;
    #pragma unroll
    for (int mi = 0; mi < 4; mi++) {
        #pragma unroll
        for (int ni = 0; ni < 4; ni++) {
            #pragma unroll
            for (int q = 0; q < 4; q++) {
                float sa = sqa[mi][q >> 1];
                float sb2 = sqb[ni][q & 1];
                float l2 = fmaf(-2.f, acc[mi][ni][q], sa + sb2);
                float tv = exp2f(l2 * c2);
                float t2 = tv * tv, t4 = t2 * t2, t8 = t4 * t4;
                local += (tv + t2) + (t4 + (t8 + t8 * t8));
            }
        }
    }
    float wgt = (((bi < NTB / 2) == (bj < NTB / 2)) ? 1.f : -1.f)
              * ((bi == bj) ? 1.f : 2.f);
    local *= wgt;

    #pragma unroll
    for (int o = 16; o > 0; o >>= 1)
        local += __shfl_down_sync(0xffffffffu, local, o);
    if (lane == 0) red[wid] = local;
    __syncthreads();
    if (tid == 0) {
        float s = 0.f;
        #pragma unroll
        for (int i = 0; i < 8; i++) s += red[i];
        atomicAdd(&g_acc, (double)s);
    }
}

__global__ void fin_kernel(float* out) {
    out[0] = (float)(g_acc / ((double)NROW * (double)NROW));
}

// ---------------------------------------------------------------------------
extern "C" void kernel_launch(void* const* d_in, const int* in_sizes, int n_in,
                              void* d_out, int out_size) {
    const float* src = (const float*)d_in[0];
    const float* tgt = (const float*)d_in[1];
    float* out = (float*)d_out;

    cudaFuncSetAttribute(mmd_mma_kernel,
                         cudaFuncAttributeMaxDynamicSharedMemorySize, 65536);

    init_kernel<<<1, 128>>>();
    stats_perm_kernel<<<NTB, 256>>>(src, tgt);
    bw_kernel<<<1, 128>>>();
    mmd_mma_kernel<<<NTILES, 256, 65536>>>();
    fin_kernel<<<1, 1>>>(out);
}